// round 10
// baseline (speedup 1.0000x reference)
#include <cuda_runtime.h>
#include <math.h>

#define BATCH 2
#define SEQ   2048
#define EMB   512
#define NH    8
#define HD    64
#define BS    (BATCH*SEQ)      /* 4096 */
#define W1LD  (EMB+NH)         /* 520  */

// ---------------- scratch (device globals; no allocation allowed) ----------------
__device__ float g_q[BS*EMB];
__device__ float g_k[BS*EMB];
__device__ float g_v[BS*EMB];
__device__ float g_scores[(size_t)BATCH*NH*SEQ*SEQ];   // 256 MiB
__device__ float g_ewm[(size_t)BATCH*SEQ*SEQ];         // mean edge weights
__device__ float g_invnn[BS];
__device__ float g_mid[BS*EMB];
__device__ float g_pre[BS*EMB];
__device__ float g_msg[BS*EMB];                        // accv + accx*invnn
__device__ float g_bm1eff[EMB];

// ---------------- fast exp on the FMA pipe (MUFU is 0.5/SM/cyc on sm_103a) -------
__device__ __forceinline__ float fast_exp(float x) {
    x = fmaxf(x, -80.0f);
    float t  = x * 1.4426950408889634f;
    float fi = floorf(t + 0.5f);
    float f  = t - fi;
    float u  = f * 0.6931471805599453f;
    float p = 1.0f + u*(1.0f + u*(0.5f + u*(0.16666667f + u*(0.041666667f + u*0.0083333333f))));
    int ei = (int)fi;
    return __int_as_float((ei + 127) << 23) * p;
}

// ================= 128x128 tile, BK=16, 8x8 microtile, double-buffered SGEMM =====
// C[M,N] = alpha * A @ op(B) + bias + res, optional exact GELU.
// TB=true:  B is [N,K] row-major (C = A @ B^T);  TB=false: B is [K,N] row-major.
// Requires: M,N multiples of 128; K multiple of 16. Grid: (N/128, M/128, Z).
template<bool TB, bool GELU>
__global__ __launch_bounds__(256, 2)
void sgemm128(const float* __restrict__ A, const float* __restrict__ B,
              const float* __restrict__ bias, const float* __restrict__ res,
              float* __restrict__ C,
              int K, int lda, int ldb, int ldc,
              long long sA, long long sB, long long sC, float alpha)
{
    __shared__ __align__(16) float As[2][16][132];
    __shared__ __align__(16) float Bs[2][16][132];

    A += (long long)blockIdx.z * sA;
    B += (long long)blockIdx.z * sB;
    C += (long long)blockIdx.z * sC;

    const int m0 = blockIdx.y * 128;
    const int n0 = blockIdx.x * 128;
    const int tid = threadIdx.x;
    const int tx = tid & 15;          // N direction (8 cols each)
    const int ty = tid >> 4;          // M direction (8 rows each)

    const int aRow = tid >> 2;
    const int aK4  = (tid & 3) << 2;
    const int bK   = tid >> 5;
    const int bN4  = (tid & 31) << 2;

    float4 a0, a1, b0, b1;

    // ---- prologue: load tile k0=0 ----
    {
        const float* Ap = A + (long long)m0 * lda;
        a0 = *(const float4*)&Ap[(long long)aRow        * lda + aK4];
        a1 = *(const float4*)&Ap[(long long)(aRow + 64) * lda + aK4];
        if (TB) {
            const float* Bp = B + (long long)n0 * ldb;
            b0 = *(const float4*)&Bp[(long long)aRow        * ldb + aK4];
            b1 = *(const float4*)&Bp[(long long)(aRow + 64) * ldb + aK4];
        } else {
            const float* Bp = B + n0;
            b0 = *(const float4*)&Bp[(long long)bK       * ldb + bN4];
            b1 = *(const float4*)&Bp[(long long)(bK + 8) * ldb + bN4];
        }
    }
    {
        As[0][aK4+0][aRow] = a0.x; As[0][aK4+1][aRow] = a0.y;
        As[0][aK4+2][aRow] = a0.z; As[0][aK4+3][aRow] = a0.w;
        As[0][aK4+0][aRow+64] = a1.x; As[0][aK4+1][aRow+64] = a1.y;
        As[0][aK4+2][aRow+64] = a1.z; As[0][aK4+3][aRow+64] = a1.w;
        if (TB) {
            Bs[0][aK4+0][aRow] = b0.x; Bs[0][aK4+1][aRow] = b0.y;
            Bs[0][aK4+2][aRow] = b0.z; Bs[0][aK4+3][aRow] = b0.w;
            Bs[0][aK4+0][aRow+64] = b1.x; Bs[0][aK4+1][aRow+64] = b1.y;
            Bs[0][aK4+2][aRow+64] = b1.z; Bs[0][aK4+3][aRow+64] = b1.w;
        } else {
            *(float4*)&Bs[0][bK    ][bN4] = b0;
            *(float4*)&Bs[0][bK + 8][bN4] = b1;
        }
    }
    __syncthreads();

    float acc[8][8];
#pragma unroll
    for (int i = 0; i < 8; i++)
#pragma unroll
        for (int j = 0; j < 8; j++) acc[i][j] = 0.0f;

    int buf = 0;
    for (int k0 = 0; k0 < K; k0 += 16) {
        const int k1 = k0 + 16;
        const bool more = (k1 < K);
        if (more) {
            const float* Ap = A + (long long)m0 * lda + k1;
            a0 = *(const float4*)&Ap[(long long)aRow        * lda + aK4];
            a1 = *(const float4*)&Ap[(long long)(aRow + 64) * lda + aK4];
            if (TB) {
                const float* Bp = B + (long long)n0 * ldb + k1;
                b0 = *(const float4*)&Bp[(long long)aRow        * ldb + aK4];
                b1 = *(const float4*)&Bp[(long long)(aRow + 64) * ldb + aK4];
            } else {
                const float* Bp = B + (long long)k1 * ldb + n0;
                b0 = *(const float4*)&Bp[(long long)bK       * ldb + bN4];
                b1 = *(const float4*)&Bp[(long long)(bK + 8) * ldb + bN4];
            }
        }

#pragma unroll
        for (int kk = 0; kk < 16; kk++) {
            float af[8], bf[8];
            *(float4*)&af[0] = *(const float4*)&As[buf][kk][ty * 8];
            *(float4*)&af[4] = *(const float4*)&As[buf][kk][ty * 8 + 4];
            *(float4*)&bf[0] = *(const float4*)&Bs[buf][kk][tx * 8];
            *(float4*)&bf[4] = *(const float4*)&Bs[buf][kk][tx * 8 + 4];
#pragma unroll
            for (int i = 0; i < 8; i++)
#pragma unroll
                for (int j = 0; j < 8; j++)
                    acc[i][j] = fmaf(af[i], bf[j], acc[i][j]);
        }

        if (more) {
            const int nb = buf ^ 1;
            As[nb][aK4+0][aRow] = a0.x; As[nb][aK4+1][aRow] = a0.y;
            As[nb][aK4+2][aRow] = a0.z; As[nb][aK4+3][aRow] = a0.w;
            As[nb][aK4+0][aRow+64] = a1.x; As[nb][aK4+1][aRow+64] = a1.y;
            As[nb][aK4+2][aRow+64] = a1.z; As[nb][aK4+3][aRow+64] = a1.w;
            if (TB) {
                Bs[nb][aK4+0][aRow] = b0.x; Bs[nb][aK4+1][aRow] = b0.y;
                Bs[nb][aK4+2][aRow] = b0.z; Bs[nb][aK4+3][aRow] = b0.w;
                Bs[nb][aK4+0][aRow+64] = b1.x; Bs[nb][aK4+1][aRow+64] = b1.y;
                Bs[nb][aK4+2][aRow+64] = b1.z; Bs[nb][aK4+3][aRow+64] = b1.w;
            } else {
                *(float4*)&Bs[nb][bK    ][bN4] = b0;
                *(float4*)&Bs[nb][bK + 8][bN4] = b1;
            }
            __syncthreads();
            buf = nb;
        }
    }

    // ---- epilogue ----
    float bb[8];
#pragma unroll
    for (int j = 0; j < 8; j++) bb[j] = bias ? bias[n0 + tx * 8 + j] : 0.0f;

#pragma unroll
    for (int i = 0; i < 8; i++) {
        const long long m = m0 + ty * 8 + i;
        float o[8];
#pragma unroll
        for (int j = 0; j < 8; j++) {
            float v = fmaf(acc[i][j], alpha, bb[j]);
            if (GELU) v = 0.5f * v * (1.0f + erff(v * 0.70710678118654752f));
            o[j] = v;
        }
        if (res) {
            float4 r0 = *(const float4*)&res[m * ldc + n0 + tx * 8];
            float4 r1 = *(const float4*)&res[m * ldc + n0 + tx * 8 + 4];
            o[0] += r0.x; o[1] += r0.y; o[2] += r0.z; o[3] += r0.w;
            o[4] += r1.x; o[5] += r1.y; o[6] += r1.z; o[7] += r1.w;
        }
        *(float4*)&C[m * ldc + n0 + tx * 8    ] = *(float4*)&o[0];
        *(float4*)&C[m * ldc + n0 + tx * 8 + 4] = *(float4*)&o[4];
    }
}

// ======= fused dual aggregation: msg = ewm@V + diag(invnn)·(mask(ewm)@X) =========
// A (ewm) loaded ONCE per tile; mask derived in-register (ALU SEL, no extra smem).
// 128x128 tile, BK=8, two 8x8 microtiles (128 acc regs). Grid (EMB/128, SEQ/128, B).
__global__ __launch_bounds__(256)
void dual_agg(const float* __restrict__ EW, const float* __restrict__ V,
              const float* __restrict__ X, const float* __restrict__ invnn,
              float* __restrict__ MSG)
{
    __shared__ __align__(16) float As [2][8][132];
    __shared__ __align__(16) float Bvs[2][8][132];
    __shared__ __align__(16) float Bxs[2][8][132];

    const int z = blockIdx.z;
    const float* A  = EW + (long long)z * SEQ * SEQ;
    const float* Bv = V  + (long long)z * SEQ * EMB;
    const float* Bx = X  + (long long)z * SEQ * EMB;
    float* C = MSG + (long long)z * SEQ * EMB;

    const int m0 = blockIdx.y * 128;
    const int n0 = blockIdx.x * 128;
    const int tid = threadIdx.x;
    const int tx = tid & 15;
    const int ty = tid >> 4;

    const int aRow = tid >> 1;            // 0..127
    const int aK4  = (tid & 1) << 2;      // 0 or 4
    const int bK   = tid >> 5;            // 0..7
    const int bN4  = (tid & 31) << 2;     // 0..124

    float4 a0, bv0, bx0;

    // prologue
    a0  = *(const float4*)&A [(long long)(m0 + aRow) * SEQ + aK4];
    bv0 = *(const float4*)&Bv[(long long)bK * EMB + n0 + bN4];
    bx0 = *(const float4*)&Bx[(long long)bK * EMB + n0 + bN4];
    As[0][aK4+0][aRow] = a0.x; As[0][aK4+1][aRow] = a0.y;
    As[0][aK4+2][aRow] = a0.z; As[0][aK4+3][aRow] = a0.w;
    *(float4*)&Bvs[0][bK][bN4] = bv0;
    *(float4*)&Bxs[0][bK][bN4] = bx0;
    __syncthreads();

    float accv[8][8], accx[8][8];
#pragma unroll
    for (int i = 0; i < 8; i++)
#pragma unroll
        for (int j = 0; j < 8; j++) { accv[i][j] = 0.0f; accx[i][j] = 0.0f; }

    int buf = 0;
    for (int k0 = 0; k0 < SEQ; k0 += 8) {
        const int k1 = k0 + 8;
        const bool more = (k1 < SEQ);
        if (more) {
            a0  = *(const float4*)&A [(long long)(m0 + aRow) * SEQ + k1 + aK4];
            bv0 = *(const float4*)&Bv[(long long)(k1 + bK) * EMB + n0 + bN4];
            bx0 = *(const float4*)&Bx[(long long)(k1 + bK) * EMB + n0 + bN4];
        }

#pragma unroll
        for (int kk = 0; kk < 8; kk++) {
            float af[8], am[8], bv[8], bx[8];
            *(float4*)&af[0] = *(const float4*)&As[buf][kk][ty * 8];
            *(float4*)&af[4] = *(const float4*)&As[buf][kk][ty * 8 + 4];
            *(float4*)&bv[0] = *(const float4*)&Bvs[buf][kk][tx * 8];
            *(float4*)&bv[4] = *(const float4*)&Bvs[buf][kk][tx * 8 + 4];
            *(float4*)&bx[0] = *(const float4*)&Bxs[buf][kk][tx * 8];
            *(float4*)&bx[4] = *(const float4*)&Bxs[buf][kk][tx * 8 + 4];
#pragma unroll
            for (int i = 0; i < 8; i++) am[i] = (af[i] > 0.1f) ? af[i] : 0.0f;
#pragma unroll
            for (int i = 0; i < 8; i++)
#pragma unroll
                for (int j = 0; j < 8; j++) {
                    accv[i][j] = fmaf(af[i], bv[j], accv[i][j]);
                    accx[i][j] = fmaf(am[i], bx[j], accx[i][j]);
                }
        }

        if (more) {
            const int nb = buf ^ 1;
            As[nb][aK4+0][aRow] = a0.x; As[nb][aK4+1][aRow] = a0.y;
            As[nb][aK4+2][aRow] = a0.z; As[nb][aK4+3][aRow] = a0.w;
            *(float4*)&Bvs[nb][bK][bN4] = bv0;
            *(float4*)&Bxs[nb][bK][bN4] = bx0;
            __syncthreads();
            buf = nb;
        }
    }

    // epilogue: msg = accv + accx * invnn[row]
#pragma unroll
    for (int i = 0; i < 8; i++) {
        const int m = m0 + ty * 8 + i;
        const float inv = invnn[z * SEQ + m];
        float o[8];
#pragma unroll
        for (int j = 0; j < 8; j++) o[j] = fmaf(accx[i][j], inv, accv[i][j]);
        *(float4*)&C[(long long)m * EMB + n0 + tx * 8    ] = *(float4*)&o[0];
        *(float4*)&C[(long long)m * EMB + n0 + tx * 8 + 4] = *(float4*)&o[4];
    }
}

// ---------------- effective MLP bias: edge_features == 1/S analytically ----------
__global__ void bm1eff_kernel(const float* __restrict__ Wm1,
                              const float* __restrict__ bm1,
                              float* __restrict__ out)
{
    int e = blockIdx.x * blockDim.x + threadIdx.x;
    if (e < EMB) {
        float s = 0.0f;
#pragma unroll
        for (int h = 0; h < NH; h++) s += Wm1[(long long)e * W1LD + EMB + h];
        out[e] = bm1[e] + s * (1.0f / (float)SEQ);
    }
}

// ---------------- softmax over j per (b,i,h); emit ew_mean + 1/nn ----------------
__global__ __launch_bounds__(256)
void softmax_ew_kernel(const float* __restrict__ scores,
                       float* __restrict__ ewm, float* __restrict__ invnn)
{
    extern __shared__ float sm[];            // NH * SEQ floats
    __shared__ float sinv[NH];
    __shared__ int   scnt[NH];

    const int bi = blockIdx.x;
    const int b  = bi / SEQ;
    const int i  = bi % SEQ;
    const int tid = threadIdx.x;

    const float* base0 = scores + ((size_t)(b * NH) * SEQ + (size_t)i) * SEQ;
    const size_t hstride = (size_t)SEQ * SEQ;

    for (int idx = tid; idx < NH * SEQ; idx += 256) {
        int h = idx >> 11;
        int j = idx & (SEQ - 1);
        sm[idx] = base0[(size_t)h * hstride + j];
    }
    __syncthreads();

    const int w = tid >> 5, lane = tid & 31;
    {
        float m = -1e30f;
        for (int j = lane; j < SEQ; j += 32) m = fmaxf(m, sm[w * SEQ + j]);
#pragma unroll
        for (int o = 16; o > 0; o >>= 1) m = fmaxf(m, __shfl_xor_sync(0xffffffffu, m, o));
        float z = 0.0f;
        for (int j = lane; j < SEQ; j += 32) {
            float e = fast_exp(sm[w * SEQ + j] - m);
            sm[w * SEQ + j] = e;
            z += e;
        }
#pragma unroll
        for (int o = 16; o > 0; o >>= 1) z += __shfl_xor_sync(0xffffffffu, z, o);
        if (lane == 0) sinv[w] = 1.0f / z;
    }
    __syncthreads();

    float inv[NH];
#pragma unroll
    for (int h = 0; h < NH; h++) inv[h] = sinv[h] * (1.0f / (float)NH);

    int cnt = 0;
    const size_t obase = (size_t)bi * SEQ;
    for (int j = tid; j < SEQ; j += 256) {
        float ew = 0.0f;
#pragma unroll
        for (int h = 0; h < NH; h++) ew += sm[h * SEQ + j] * inv[h];
        ewm[obase + j] = ew;
        cnt += (ew > 0.1f) ? 1 : 0;
    }
#pragma unroll
    for (int o = 16; o > 0; o >>= 1) cnt += __shfl_xor_sync(0xffffffffu, cnt, o);
    if (lane == 0) scnt[w] = cnt;
    __syncthreads();
    if (tid == 0) {
        int c = 0;
#pragma unroll
        for (int h = 0; h < NH; h++) c += scnt[h];
        float f = (float)c;
        if (f < 1.0f) f = 1.0f;
        invnn[bi] = 1.0f / f;
    }
}

// ---------------- driver ---------------------------------------------------------
extern "C" void kernel_launch(void* const* d_in, const int* in_sizes, int n_in,
                              void* d_out, int out_size)
{
    const float* x   = (const float*)d_in[0];
    const float* Wq  = (const float*)d_in[1];
    const float* bq  = (const float*)d_in[2];
    const float* Wk  = (const float*)d_in[3];
    const float* bk  = (const float*)d_in[4];
    const float* Wv  = (const float*)d_in[5];
    const float* bv  = (const float*)d_in[6];
    const float* Wm1 = (const float*)d_in[7];
    const float* bm1 = (const float*)d_in[8];
    const float* Wm2 = (const float*)d_in[9];
    const float* bm2 = (const float*)d_in[10];
    const float* Wo  = (const float*)d_in[11];
    const float* bo  = (const float*)d_in[12];
    float* out = (float*)d_out;

    float *q, *k, *v, *scores, *ewm, *invnn, *mid, *pre, *msg, *bm1eff;
    cudaGetSymbolAddress((void**)&q,      g_q);
    cudaGetSymbolAddress((void**)&k,      g_k);
    cudaGetSymbolAddress((void**)&v,      g_v);
    cudaGetSymbolAddress((void**)&scores, g_scores);
    cudaGetSymbolAddress((void**)&ewm,    g_ewm);
    cudaGetSymbolAddress((void**)&invnn,  g_invnn);
    cudaGetSymbolAddress((void**)&mid,    g_mid);
    cudaGetSymbolAddress((void**)&pre,    g_pre);
    cudaGetSymbolAddress((void**)&msg,    g_msg);
    cudaGetSymbolAddress((void**)&bm1eff, g_bm1eff);

    // effective MLP bias (edge_features == 1/S analytically)
    bm1eff_kernel<<<1, 512>>>(Wm1, bm1, bm1eff);

    // QKV projections: [4096,512] = x @ W^T + b
    dim3 gP(EMB / 128, BS / 128, 1);
    sgemm128<true,  false><<<gP, 256>>>(x, Wq, bq, nullptr, q, EMB, EMB, EMB, EMB, 0, 0, 0, 1.0f);
    sgemm128<true,  false><<<gP, 256>>>(x, Wk, bk, nullptr, k, EMB, EMB, EMB, EMB, 0, 0, 0, 1.0f);
    sgemm128<true,  false><<<gP, 256>>>(x, Wv, bv, nullptr, v, EMB, EMB, EMB, EMB, 0, 0, 0, 1.0f);

    // scores[b,h] = scale * q_h @ k_h^T  (z = head; per-batch launch)
    dim3 gS(SEQ / 128, SEQ / 128, NH);
    for (int b = 0; b < BATCH; b++) {
        sgemm128<true, false><<<gS, 256>>>(
            q + (size_t)b * SEQ * EMB, k + (size_t)b * SEQ * EMB, nullptr, nullptr,
            scores + (size_t)b * NH * SEQ * SEQ,
            HD, EMB, EMB, SEQ,
            64LL, 64LL, (long long)SEQ * SEQ, 0.125f);
    }

    // softmax + mean-over-heads + neighbor counts
    cudaFuncSetAttribute(softmax_ew_kernel,
                         cudaFuncAttributeMaxDynamicSharedMemorySize, NH * SEQ * 4);
    softmax_ew_kernel<<<BS, 256, NH * SEQ * 4>>>(scores, ewm, invnn);

    // fused: msg = ewm@v + diag(invnn)*(mask(ewm)@x)
    dim3 gA(EMB / 128, SEQ / 128, BATCH);
    dual_agg<<<gA, 256>>>(ewm, v, x, invnn, msg);

    // gated MLP: mid = gelu(x @ Wm1[:, :E]^T + bm1_eff); pre = mid @ Wm2^T + bm2 + msg
    sgemm128<true, true ><<<gP, 256>>>(x,   Wm1, bm1eff, nullptr, mid, EMB, EMB, W1LD, EMB, 0, 0, 0, 1.0f);
    sgemm128<true, false><<<gP, 256>>>(mid, Wm2, bm2,    msg,     pre, EMB, EMB, EMB,  EMB, 0, 0, 0, 1.0f);

    // out = pre @ Wo^T + bo
    sgemm128<true, false><<<gP, 256>>>(pre, Wo, bo, nullptr, out, EMB, EMB, EMB, EMB, 0, 0, 0, 1.0f);
}

// round 15
// speedup vs baseline: 1.1348x; 1.1348x over previous
#include <cuda_runtime.h>
#include <math.h>

#define BATCH 2
#define SEQ   2048
#define EMB   512
#define NH    8
#define HD    64
#define BS    (BATCH*SEQ)      /* 4096 */
#define W1LD  (EMB+NH)         /* 520  */

// ---------------- scratch (device globals; no allocation allowed) ----------------
__device__ float g_q[BS*EMB];
__device__ float g_k[BS*EMB];
__device__ float g_v[BS*EMB];
__device__ float g_scores[(size_t)BATCH*NH*SEQ*SEQ];   // 256 MiB
__device__ float g_ewm[(size_t)BATCH*SEQ*SEQ];         // mean edge weights
__device__ float g_invnn[BS];
__device__ float g_mid[BS*EMB];
__device__ float g_pre[BS*EMB];
__device__ float g_msg[BS*EMB];                        // accv + accx*invnn
__device__ float g_bm1eff[EMB];

// ---------------- fast exp on the FMA pipe (MUFU is 0.5/SM/cyc on sm_103a) -------
__device__ __forceinline__ float fast_exp(float x) {
    x = fmaxf(x, -80.0f);
    float t  = x * 1.4426950408889634f;
    float fi = floorf(t + 0.5f);
    float f  = t - fi;
    float u  = f * 0.6931471805599453f;
    float p = 1.0f + u*(1.0f + u*(0.5f + u*(0.16666667f + u*(0.041666667f + u*0.0083333333f))));
    int ei = (int)fi;
    return __int_as_float((ei + 127) << 23) * p;
}

// ================= shared GEMM body: 128x128 tile, BK=16, split 4+4 microtile ====
// Conflict-free LDS: fragments read at ty*4 / ty*4+64 (A) and tx*4 / tx*4+64 (B),
// so each 8-lane LDS.128 phase covers all 32 banks.
// TB=true:  B is [N,K] row-major (C = A @ B^T);  TB=false: B is [K,N] row-major.
// Requires: M,N multiples of 128; K multiple of 16.
template<bool TB, bool GELU>
__device__ __forceinline__ void gemm_body(
    const float* __restrict__ A, const float* __restrict__ B,
    const float* __restrict__ bias, const float* __restrict__ res,
    float* __restrict__ C, int K, int lda, int ldb, int ldc,
    int m0, int n0, float alpha)
{
    __shared__ __align__(16) float As[2][16][132];
    __shared__ __align__(16) float Bs[2][16][132];

    const int tid = threadIdx.x;
    const int tx = tid & 15;          // N direction
    const int ty = tid >> 4;          // M direction

    const int aRow = tid >> 2;
    const int aK4  = (tid & 3) << 2;
    const int bK   = tid >> 5;
    const int bN4  = (tid & 31) << 2;

    float4 a0, a1, b0, b1;

    // ---- prologue: load tile k0=0 ----
    {
        const float* Ap = A + (long long)m0 * lda;
        a0 = *(const float4*)&Ap[(long long)aRow        * lda + aK4];
        a1 = *(const float4*)&Ap[(long long)(aRow + 64) * lda + aK4];
        if (TB) {
            const float* Bp = B + (long long)n0 * ldb;
            b0 = *(const float4*)&Bp[(long long)aRow        * ldb + aK4];
            b1 = *(const float4*)&Bp[(long long)(aRow + 64) * ldb + aK4];
        } else {
            const float* Bp = B + n0;
            b0 = *(const float4*)&Bp[(long long)bK       * ldb + bN4];
            b1 = *(const float4*)&Bp[(long long)(bK + 8) * ldb + bN4];
        }
    }
    {
        As[0][aK4+0][aRow] = a0.x; As[0][aK4+1][aRow] = a0.y;
        As[0][aK4+2][aRow] = a0.z; As[0][aK4+3][aRow] = a0.w;
        As[0][aK4+0][aRow+64] = a1.x; As[0][aK4+1][aRow+64] = a1.y;
        As[0][aK4+2][aRow+64] = a1.z; As[0][aK4+3][aRow+64] = a1.w;
        if (TB) {
            Bs[0][aK4+0][aRow] = b0.x; Bs[0][aK4+1][aRow] = b0.y;
            Bs[0][aK4+2][aRow] = b0.z; Bs[0][aK4+3][aRow] = b0.w;
            Bs[0][aK4+0][aRow+64] = b1.x; Bs[0][aK4+1][aRow+64] = b1.y;
            Bs[0][aK4+2][aRow+64] = b1.z; Bs[0][aK4+3][aRow+64] = b1.w;
        } else {
            *(float4*)&Bs[0][bK    ][bN4] = b0;
            *(float4*)&Bs[0][bK + 8][bN4] = b1;
        }
    }
    __syncthreads();

    float acc[8][8];
#pragma unroll
    for (int i = 0; i < 8; i++)
#pragma unroll
        for (int j = 0; j < 8; j++) acc[i][j] = 0.0f;

    int buf = 0;
    for (int k0 = 0; k0 < K; k0 += 16) {
        const int k1 = k0 + 16;
        const bool more = (k1 < K);
        if (more) {
            const float* Ap = A + (long long)m0 * lda + k1;
            a0 = *(const float4*)&Ap[(long long)aRow        * lda + aK4];
            a1 = *(const float4*)&Ap[(long long)(aRow + 64) * lda + aK4];
            if (TB) {
                const float* Bp = B + (long long)n0 * ldb + k1;
                b0 = *(const float4*)&Bp[(long long)aRow        * ldb + aK4];
                b1 = *(const float4*)&Bp[(long long)(aRow + 64) * ldb + aK4];
            } else {
                const float* Bp = B + (long long)k1 * ldb + n0;
                b0 = *(const float4*)&Bp[(long long)bK       * ldb + bN4];
                b1 = *(const float4*)&Bp[(long long)(bK + 8) * ldb + bN4];
            }
        }

#pragma unroll
        for (int kk = 0; kk < 16; kk++) {
            float af[8], bf[8];
            *(float4*)&af[0] = *(const float4*)&As[buf][kk][ty * 4];
            *(float4*)&af[4] = *(const float4*)&As[buf][kk][ty * 4 + 64];
            *(float4*)&bf[0] = *(const float4*)&Bs[buf][kk][tx * 4];
            *(float4*)&bf[4] = *(const float4*)&Bs[buf][kk][tx * 4 + 64];
#pragma unroll
            for (int i = 0; i < 8; i++)
#pragma unroll
                for (int j = 0; j < 8; j++)
                    acc[i][j] = fmaf(af[i], bf[j], acc[i][j]);
        }

        if (more) {
            const int nb = buf ^ 1;
            As[nb][aK4+0][aRow] = a0.x; As[nb][aK4+1][aRow] = a0.y;
            As[nb][aK4+2][aRow] = a0.z; As[nb][aK4+3][aRow] = a0.w;
            As[nb][aK4+0][aRow+64] = a1.x; As[nb][aK4+1][aRow+64] = a1.y;
            As[nb][aK4+2][aRow+64] = a1.z; As[nb][aK4+3][aRow+64] = a1.w;
            if (TB) {
                Bs[nb][aK4+0][aRow] = b0.x; Bs[nb][aK4+1][aRow] = b0.y;
                Bs[nb][aK4+2][aRow] = b0.z; Bs[nb][aK4+3][aRow] = b0.w;
                Bs[nb][aK4+0][aRow+64] = b1.x; Bs[nb][aK4+1][aRow+64] = b1.y;
                Bs[nb][aK4+2][aRow+64] = b1.z; Bs[nb][aK4+3][aRow+64] = b1.w;
            } else {
                *(float4*)&Bs[nb][bK    ][bN4] = b0;
                *(float4*)&Bs[nb][bK + 8][bN4] = b1;
            }
            __syncthreads();
            buf = nb;
        }
    }

    // ---- epilogue (split 4+4 in both M and N) ----
    float bb0[4], bb1[4];
#pragma unroll
    for (int j = 0; j < 4; j++) {
        bb0[j] = bias ? bias[n0 + tx * 4 + j]      : 0.0f;
        bb1[j] = bias ? bias[n0 + 64 + tx * 4 + j] : 0.0f;
    }

#pragma unroll
    for (int ih = 0; ih < 2; ih++) {
#pragma unroll
        for (int i = 0; i < 4; i++) {
            const long long m = m0 + ih * 64 + ty * 4 + i;
            const int ia = ih * 4 + i;
            float o0[4], o1[4];
#pragma unroll
            for (int j = 0; j < 4; j++) {
                float v0 = fmaf(acc[ia][j],     alpha, bb0[j]);
                float v1 = fmaf(acc[ia][j + 4], alpha, bb1[j]);
                if (GELU) {
                    v0 = 0.5f * v0 * (1.0f + erff(v0 * 0.70710678118654752f));
                    v1 = 0.5f * v1 * (1.0f + erff(v1 * 0.70710678118654752f));
                }
                o0[j] = v0; o1[j] = v1;
            }
            if (res) {
                float4 r0 = *(const float4*)&res[m * ldc + n0 + tx * 4];
                float4 r1 = *(const float4*)&res[m * ldc + n0 + 64 + tx * 4];
                o0[0] += r0.x; o0[1] += r0.y; o0[2] += r0.z; o0[3] += r0.w;
                o1[0] += r1.x; o1[1] += r1.y; o1[2] += r1.z; o1[3] += r1.w;
            }
            *(float4*)&C[m * ldc + n0 + tx * 4     ] = *(float4*)&o0[0];
            *(float4*)&C[m * ldc + n0 + 64 + tx * 4] = *(float4*)&o1[0];
        }
    }
}

// ---- generic wrapper ----
template<bool TB, bool GELU>
__global__ __launch_bounds__(256)
void sgemm128(const float* __restrict__ A, const float* __restrict__ B,
              const float* __restrict__ bias, const float* __restrict__ res,
              float* __restrict__ C,
              int K, int lda, int ldb, int ldc,
              long long sA, long long sB, long long sC, float alpha)
{
    gemm_body<TB, GELU>(A + (long long)blockIdx.z * sA,
                        B + (long long)blockIdx.z * sB,
                        bias, res ? res + (long long)blockIdx.z * sC : nullptr,
                        C + (long long)blockIdx.z * sC,
                        K, lda, ldb, ldc,
                        blockIdx.y * 128, blockIdx.x * 128, alpha);
}

// ---- fused QKV: seg = blockIdx.x>>2 selects weight/bias/output; grid (12, 32) ----
__global__ __launch_bounds__(256)
void qkv_gemm(const float* __restrict__ x,
              const float* __restrict__ Wq, const float* __restrict__ bq,
              const float* __restrict__ Wk, const float* __restrict__ bk,
              const float* __restrict__ Wv, const float* __restrict__ bv,
              float* __restrict__ q, float* __restrict__ k, float* __restrict__ v)
{
    const int seg = blockIdx.x >> 2;
    const float* W = (seg == 0) ? Wq : (seg == 1) ? Wk : Wv;
    const float* b = (seg == 0) ? bq : (seg == 1) ? bk : bv;
    float*     out = (seg == 0) ? q  : (seg == 1) ? k  : v;
    gemm_body<true, false>(x, W, b, nullptr, out,
                           EMB, EMB, EMB, EMB,
                           blockIdx.y * 128, (blockIdx.x & 3) * 128, 1.0f);
}

// ======= fused dual aggregation: msg = ewm@V + diag(invnn)·(mask(ewm)@X) =========
// A (ewm) loaded ONCE per tile; mask derived in-register. Split 4+4 microtile.
__global__ __launch_bounds__(256)
void dual_agg(const float* __restrict__ EW, const float* __restrict__ V,
              const float* __restrict__ X, const float* __restrict__ invnn,
              float* __restrict__ MSG)
{
    __shared__ __align__(16) float As [2][8][132];
    __shared__ __align__(16) float Bvs[2][8][132];
    __shared__ __align__(16) float Bxs[2][8][132];

    const int z = blockIdx.z;
    const float* A  = EW + (long long)z * SEQ * SEQ;
    const float* Bv = V  + (long long)z * SEQ * EMB;
    const float* Bx = X  + (long long)z * SEQ * EMB;
    float* C = MSG + (long long)z * SEQ * EMB;

    const int m0 = blockIdx.y * 128;
    const int n0 = blockIdx.x * 128;
    const int tid = threadIdx.x;
    const int tx = tid & 15;
    const int ty = tid >> 4;

    const int aRow = tid >> 1;            // 0..127
    const int aK4  = (tid & 1) << 2;      // 0 or 4
    const int bK   = tid >> 5;            // 0..7
    const int bN4  = (tid & 31) << 2;     // 0..124

    float4 a0, bv0, bx0;

    // prologue
    a0  = *(const float4*)&A [(long long)(m0 + aRow) * SEQ + aK4];
    bv0 = *(const float4*)&Bv[(long long)bK * EMB + n0 + bN4];
    bx0 = *(const float4*)&Bx[(long long)bK * EMB + n0 + bN4];
    As[0][aK4+0][aRow] = a0.x; As[0][aK4+1][aRow] = a0.y;
    As[0][aK4+2][aRow] = a0.z; As[0][aK4+3][aRow] = a0.w;
    *(float4*)&Bvs[0][bK][bN4] = bv0;
    *(float4*)&Bxs[0][bK][bN4] = bx0;
    __syncthreads();

    float accv[8][8], accx[8][8];
#pragma unroll
    for (int i = 0; i < 8; i++)
#pragma unroll
        for (int j = 0; j < 8; j++) { accv[i][j] = 0.0f; accx[i][j] = 0.0f; }

    int buf = 0;
    for (int k0 = 0; k0 < SEQ; k0 += 8) {
        const int k1 = k0 + 8;
        const bool more = (k1 < SEQ);
        if (more) {
            a0  = *(const float4*)&A [(long long)(m0 + aRow) * SEQ + k1 + aK4];
            bv0 = *(const float4*)&Bv[(long long)(k1 + bK) * EMB + n0 + bN4];
            bx0 = *(const float4*)&Bx[(long long)(k1 + bK) * EMB + n0 + bN4];
        }

#pragma unroll
        for (int kk = 0; kk < 8; kk++) {
            float af[8], am[8], bv[8], bx[8];
            *(float4*)&af[0] = *(const float4*)&As[buf][kk][ty * 4];
            *(float4*)&af[4] = *(const float4*)&As[buf][kk][ty * 4 + 64];
            *(float4*)&bv[0] = *(const float4*)&Bvs[buf][kk][tx * 4];
            *(float4*)&bv[4] = *(const float4*)&Bvs[buf][kk][tx * 4 + 64];
            *(float4*)&bx[0] = *(const float4*)&Bxs[buf][kk][tx * 4];
            *(float4*)&bx[4] = *(const float4*)&Bxs[buf][kk][tx * 4 + 64];
#pragma unroll
            for (int i = 0; i < 8; i++) am[i] = (af[i] > 0.1f) ? af[i] : 0.0f;
#pragma unroll
            for (int i = 0; i < 8; i++)
#pragma unroll
                for (int j = 0; j < 8; j++) {
                    accv[i][j] = fmaf(af[i], bv[j], accv[i][j]);
                    accx[i][j] = fmaf(am[i], bx[j], accx[i][j]);
                }
        }

        if (more) {
            const int nb = buf ^ 1;
            As[nb][aK4+0][aRow] = a0.x; As[nb][aK4+1][aRow] = a0.y;
            As[nb][aK4+2][aRow] = a0.z; As[nb][aK4+3][aRow] = a0.w;
            *(float4*)&Bvs[nb][bK][bN4] = bv0;
            *(float4*)&Bxs[nb][bK][bN4] = bx0;
            __syncthreads();
            buf = nb;
        }
    }

    // epilogue: msg = accv + accx * invnn[row]   (split 4+4)
#pragma unroll
    for (int ih = 0; ih < 2; ih++) {
#pragma unroll
        for (int i = 0; i < 4; i++) {
            const int m = m0 + ih * 64 + ty * 4 + i;
            const int ia = ih * 4 + i;
            const float inv = invnn[z * SEQ + m];
            float o0[4], o1[4];
#pragma unroll
            for (int j = 0; j < 4; j++) {
                o0[j] = fmaf(accx[ia][j],     inv, accv[ia][j]);
                o1[j] = fmaf(accx[ia][j + 4], inv, accv[ia][j + 4]);
            }
            *(float4*)&C[(long long)m * EMB + n0 + tx * 4     ] = *(float4*)&o0[0];
            *(float4*)&C[(long long)m * EMB + n0 + 64 + tx * 4] = *(float4*)&o1[0];
        }
    }
}

// ---------------- effective MLP bias: edge_features == 1/S analytically ----------
__global__ void bm1eff_kernel(const float* __restrict__ Wm1,
                              const float* __restrict__ bm1,
                              float* __restrict__ out)
{
    int e = blockIdx.x * blockDim.x + threadIdx.x;
    if (e < EMB) {
        float s = 0.0f;
#pragma unroll
        for (int h = 0; h < NH; h++) s += Wm1[(long long)e * W1LD + EMB + h];
        out[e] = bm1[e] + s * (1.0f / (float)SEQ);
    }
}

// ---------------- softmax over j per (b,i,h); emit ew_mean + 1/nn ----------------
__global__ __launch_bounds__(256)
void softmax_ew_kernel(const float* __restrict__ scores,
                       float* __restrict__ ewm, float* __restrict__ invnn)
{
    extern __shared__ float sm[];            // NH * SEQ floats
    __shared__ float sinv[NH];
    __shared__ int   scnt[NH];

    const int bi = blockIdx.x;
    const int b  = bi / SEQ;
    const int i  = bi % SEQ;
    const int tid = threadIdx.x;

    const float* base0 = scores + ((size_t)(b * NH) * SEQ + (size_t)i) * SEQ;
    const size_t hstride = (size_t)SEQ * SEQ;

    for (int idx = tid; idx < NH * SEQ; idx += 256) {
        int h = idx >> 11;
        int j = idx & (SEQ - 1);
        sm[idx] = base0[(size_t)h * hstride + j];
    }
    __syncthreads();

    const int w = tid >> 5, lane = tid & 31;
    {
        float m = -1e30f;
        for (int j = lane; j < SEQ; j += 32) m = fmaxf(m, sm[w * SEQ + j]);
#pragma unroll
        for (int o = 16; o > 0; o >>= 1) m = fmaxf(m, __shfl_xor_sync(0xffffffffu, m, o));
        float z = 0.0f;
        for (int j = lane; j < SEQ; j += 32) {
            float e = fast_exp(sm[w * SEQ + j] - m);
            sm[w * SEQ + j] = e;
            z += e;
        }
#pragma unroll
        for (int o = 16; o > 0; o >>= 1) z += __shfl_xor_sync(0xffffffffu, z, o);
        if (lane == 0) sinv[w] = 1.0f / z;
    }
    __syncthreads();

    float inv[NH];
#pragma unroll
    for (int h = 0; h < NH; h++) inv[h] = sinv[h] * (1.0f / (float)NH);

    int cnt = 0;
    const size_t obase = (size_t)bi * SEQ;
    for (int j = tid; j < SEQ; j += 256) {
        float ew = 0.0f;
#pragma unroll
        for (int h = 0; h < NH; h++) ew += sm[h * SEQ + j] * inv[h];
        ewm[obase + j] = ew;
        cnt += (ew > 0.1f) ? 1 : 0;
    }
#pragma unroll
    for (int o = 16; o > 0; o >>= 1) cnt += __shfl_xor_sync(0xffffffffu, cnt, o);
    if (lane == 0) scnt[w] = cnt;
    __syncthreads();
    if (tid == 0) {
        int c = 0;
#pragma unroll
        for (int h = 0; h < NH; h++) c += scnt[h];
        float f = (float)c;
        if (f < 1.0f) f = 1.0f;
        invnn[bi] = 1.0f / f;
    }
}

// ---------------- driver ---------------------------------------------------------
extern "C" void kernel_launch(void* const* d_in, const int* in_sizes, int n_in,
                              void* d_out, int out_size)
{
    const float* x   = (const float*)d_in[0];
    const float* Wq  = (const float*)d_in[1];
    const float* bq  = (const float*)d_in[2];
    const float* Wk  = (const float*)d_in[3];
    const float* bk  = (const float*)d_in[4];
    const float* Wv  = (const float*)d_in[5];
    const float* bv  = (const float*)d_in[6];
    const float* Wm1 = (const float*)d_in[7];
    const float* bm1 = (const float*)d_in[8];
    const float* Wm2 = (const float*)d_in[9];
    const float* bm2 = (const float*)d_in[10];
    const float* Wo  = (const float*)d_in[11];
    const float* bo  = (const float*)d_in[12];
    float* out = (float*)d_out;

    float *q, *k, *v, *scores, *ewm, *invnn, *mid, *pre, *msg, *bm1eff;
    cudaGetSymbolAddress((void**)&q,      g_q);
    cudaGetSymbolAddress((void**)&k,      g_k);
    cudaGetSymbolAddress((void**)&v,      g_v);
    cudaGetSymbolAddress((void**)&scores, g_scores);
    cudaGetSymbolAddress((void**)&ewm,    g_ewm);
    cudaGetSymbolAddress((void**)&invnn,  g_invnn);
    cudaGetSymbolAddress((void**)&mid,    g_mid);
    cudaGetSymbolAddress((void**)&pre,    g_pre);
    cudaGetSymbolAddress((void**)&msg,    g_msg);
    cudaGetSymbolAddress((void**)&bm1eff, g_bm1eff);

    // effective MLP bias (edge_features == 1/S analytically)
    bm1eff_kernel<<<1, 512>>>(Wm1, bm1, bm1eff);

    // fused QKV projections: grid (3*4, 32)
    dim3 gQKV(3 * (EMB / 128), BS / 128, 1);
    qkv_gemm<<<gQKV, 256>>>(x, Wq, bq, Wk, bk, Wv, bv, q, k, v);

    // scores[b,h] = scale * q_h @ k_h^T  (z = head; per-batch launch)
    dim3 gS(SEQ / 128, SEQ / 128, NH);
    for (int b = 0; b < BATCH; b++) {
        sgemm128<true, false><<<gS, 256>>>(
            q + (size_t)b * SEQ * EMB, k + (size_t)b * SEQ * EMB, nullptr, nullptr,
            scores + (size_t)b * NH * SEQ * SEQ,
            HD, EMB, EMB, SEQ,
            64LL, 64LL, (long long)SEQ * SEQ, 0.125f);
    }

    // softmax + mean-over-heads + neighbor counts
    cudaFuncSetAttribute(softmax_ew_kernel,
                         cudaFuncAttributeMaxDynamicSharedMemorySize, NH * SEQ * 4);
    softmax_ew_kernel<<<BS, 256, NH * SEQ * 4>>>(scores, ewm, invnn);

    // fused: msg = ewm@v + diag(invnn)*(mask(ewm)@x)
    dim3 gA(EMB / 128, SEQ / 128, BATCH);
    dual_agg<<<gA, 256>>>(ewm, v, x, invnn, msg);

    // gated MLP: mid = gelu(x @ Wm1[:, :E]^T + bm1_eff); pre = mid @ Wm2^T + bm2 + msg
    dim3 gP(EMB / 128, BS / 128, 1);
    sgemm128<true, true ><<<gP, 256>>>(x,   Wm1, bm1eff, nullptr, mid, EMB, EMB, W1LD, EMB, 0, 0, 0, 1.0f);
    sgemm128<true, false><<<gP, 256>>>(mid, Wm2, bm2,    msg,     pre, EMB, EMB, EMB,  EMB, 0, 0, 0, 1.0f);

    // out = pre @ Wo^T + bo
    sgemm128<true, false><<<gP, 256>>>(pre, Wo, bo, nullptr, out, EMB, EMB, EMB, EMB, 0, 0, 0, 1.0f);
}